// round 11
// baseline (speedup 1.0000x reference)
#include <cuda_runtime.h>

#define N_TOKENS 2048   // 8 * 256
#define DIM 128
#define DC 16
#define TPG 2                       // tokens per 128-thread group
#define GROUPS 2                    // groups per block
#define BLOCK_THREADS (GROUPS * DIM)            // 256
#define TOKENS_PER_BLOCK (GROUPS * TPG)         // 4
#define GRID_BLOCKS (N_TOKENS / TOKENS_PER_BLOCK)   // 512

__global__ void __launch_bounds__(BLOCK_THREADS) flf_quant_k10(
    const float* __restrict__ x,      // [2048, 128]
    const float* __restrict__ W_in,   // [128, 16]
    const float* __restrict__ b_in,   // [16]
    const float* __restrict__ W_out,  // [16, 128]
    const float* __restrict__ b_out,  // [128]
    float* __restrict__ out,          // [2048*128 (+ 2048 indices)]
    int write_indices)
{
    // floats: offset = group*128 + warp*32 + tok*16 + e
    __shared__ float2 sm[GROUPS][4][TPG][8];

    const int t = threadIdx.x;
    const int group = t >> 7;          // 0..1
    const int tg = t & 127;            // thread-in-group
    const int lane = t & 31;
    const int warp = tg >> 5;          // warp-in-group 0..3
    const unsigned FULL = 0xFFFFFFFFu;

    const int token0 = blockIdx.x * TOKENS_PER_BLOCK + group * TPG;

    const int ep  = tg & 7;            // e-pair: covers e = 2*ep, 2*ep+1
    const int cpl = (tg >> 3) & 3;     // 8-dim chunk within the warp's 32 dims
    const int dbase = warp * 32 + cpl * 8;

    // ---- direct x loads: 8 dims this thread needs, both tokens (4x LDG.128) ----
    const float4* xq = reinterpret_cast<const float4*>(x + (size_t)token0 * DIM);
    const int qb = dbase >> 2;
    float4 xa0 = xq[qb],      xb0 = xq[qb + 1];        // token0
    float4 xa1 = xq[32 + qb], xb1 = xq[32 + qb + 1];   // token1

    // ---- W_in as float2: W_in[d][2ep..2ep+1], d = dbase..dbase+7 ----
    const float2* Wi2 = reinterpret_cast<const float2*>(W_in);
    float2 wi[8];
    #pragma unroll
    for (int i = 0; i < 8; i++) wi[i] = Wi2[(dbase + i) * (DC / 2) + ep];

    // ---- mask-independent W_out / bias prefetch ----
    float wo[DC];
    #pragma unroll
    for (int e = 0; e < DC; e++) wo[e] = W_out[e * DIM + tg];
    float bo = b_out[tg];

    // ---- z partials: 8 dims x 2 e's x 2 tokens = 32 FMAs ----
    float2 p0 = make_float2(0.f, 0.f), p1 = make_float2(0.f, 0.f);
    #define STEP(XV0, XV1, I) \
        p0.x = fmaf((XV0), wi[I].x, p0.x); p0.y = fmaf((XV0), wi[I].y, p0.y); \
        p1.x = fmaf((XV1), wi[I].x, p1.x); p1.y = fmaf((XV1), wi[I].y, p1.y);
    STEP(xa0.x, xa1.x, 0) STEP(xa0.y, xa1.y, 1)
    STEP(xa0.z, xa1.z, 2) STEP(xa0.w, xa1.w, 3)
    STEP(xb0.x, xb1.x, 4) STEP(xb0.y, xb1.y, 5)
    STEP(xb0.z, xb1.z, 6) STEP(xb0.w, xb1.w, 7)
    #undef STEP

    // ---- warp pre-reduce over the 4 chunks (xor 8, then 16): 8 shfls ----
    p0.x += __shfl_xor_sync(FULL, p0.x, 8);
    p0.y += __shfl_xor_sync(FULL, p0.y, 8);
    p1.x += __shfl_xor_sync(FULL, p1.x, 8);
    p1.y += __shfl_xor_sync(FULL, p1.y, 8);
    p0.x += __shfl_xor_sync(FULL, p0.x, 16);
    p0.y += __shfl_xor_sync(FULL, p0.y, 16);
    p1.x += __shfl_xor_sync(FULL, p1.x, 16);
    p1.y += __shfl_xor_sync(FULL, p1.y, 16);

    if (lane < 8) {
        sm[group][warp][0][ep] = p0;
        sm[group][warp][1][ep] = p1;
    }
    __syncthreads();

    // ---- split-half final reduce: lane l -> token l>>4, dim l&15.
    //      float offset = group*128 + w*32 + lane  (uniform, conflict-free) ----
    const float* smf = reinterpret_cast<const float*>(sm) + group * 128;
    float z = ((smf[lane] + smf[32 + lane]) + (smf[64 + lane] + smf[96 + lane]))
            + b_in[lane & 15];

    // one ballot per warp gives both masks of its group
    unsigned b = __ballot_sync(FULL, z > 0.0f);
    unsigned mask0 = b & 0xFFFFu;
    unsigned mask1 = b >> 16;

    // ---- out dim tg for both tokens; two accumulator chains per token ----
    float a0 = bo, c0 = 0.f, a1 = bo, c1 = 0.f;
    #define ACC(E, A0, A1) { \
        float s0 = (mask0 & (1u << (E))) ? 1.0f : -1.0f; \
        float s1 = (mask1 & (1u << (E))) ? 1.0f : -1.0f; \
        A0 = fmaf(s0, wo[E], A0); \
        A1 = fmaf(s1, wo[E], A1); }
    ACC(0,  a0, a1); ACC(1,  c0, c1);
    ACC(2,  a0, a1); ACC(3,  c0, c1);
    ACC(4,  a0, a1); ACC(5,  c0, c1);
    ACC(6,  a0, a1); ACC(7,  c0, c1);
    ACC(8,  a0, a1); ACC(9,  c0, c1);
    ACC(10, a0, a1); ACC(11, c0, c1);
    ACC(12, a0, a1); ACC(13, c0, c1);
    ACC(14, a0, a1); ACC(15, c0, c1);
    #undef ACC

    float* op = out + (size_t)token0 * DIM;
    op[tg]       = a0 + c0;
    op[DIM + tg] = a1 + c1;

    if (write_indices && tg == 0) {
        float2 idx = make_float2((float)(__brev(mask0) >> 16),
                                 (float)(__brev(mask1) >> 16));
        *reinterpret_cast<float2*>(out + (size_t)N_TOKENS * DIM + token0) = idx;
    }
}

extern "C" void kernel_launch(void* const* d_in, const int* in_sizes, int n_in,
                              void* d_out, int out_size)
{
    const float* x     = (const float*)d_in[0];
    const float* W_in  = (const float*)d_in[1];
    const float* b_in  = (const float*)d_in[2];
    const float* W_out = (const float*)d_in[3];
    const float* b_out = (const float*)d_in[4];
    float* out = (float*)d_out;

    int write_indices = (out_size >= N_TOKENS * DIM + N_TOKENS) ? 1 : 0;

    flf_quant_k10<<<GRID_BLOCKS, BLOCK_THREADS>>>(
        x, W_in, b_in, W_out, b_out, out, write_indices);
}

// round 12
// speedup vs baseline: 1.3623x; 1.3623x over previous
#include <cuda_runtime.h>

#define N_TOKENS 2048   // 8 * 256
#define DIM 128
#define DC 16
#define TPB 2           // tokens per block
#define GRID_BLOCKS (N_TOKENS / TPB)   // 1024

__global__ void __launch_bounds__(DIM) flf_quant_k11(
    const float* __restrict__ x,      // [2048, 128]
    const float* __restrict__ W_in,   // [128, 16]
    const float* __restrict__ b_in,   // [16]
    const float* __restrict__ W_out,  // [16, 128]
    const float* __restrict__ b_out,  // [128]
    float* __restrict__ out,          // [2048*128 (+ 2048 indices)]
    int write_indices)
{
    // floats laid out as [warp][token][e]: offset = warp*32 + tok*16 + e
    __shared__ float2 sm[4][TPB][8];

    const int token0 = blockIdx.x * TPB;
    const int t = threadIdx.x;
    const int lane = t & 31;
    const int warp = t >> 5;
    const unsigned FULL = 0xFFFFFFFFu;

    const int ep  = t & 7;           // e-pair: covers e = 2*ep, 2*ep+1
    const int cpl = (t >> 3) & 3;    // 8-dim chunk within the warp's 32 dims
    const int dbase = warp * 32 + cpl * 8;

    // ---- direct x loads: the 8 dims this thread needs, both tokens (4x LDG.128,
    //      8 threads/chunk share addresses -> L1 broadcast) ----
    const float4* xq = reinterpret_cast<const float4*>(x + (size_t)token0 * DIM);
    const int qb = dbase >> 2;
    float4 xa0 = xq[qb],      xb0 = xq[qb + 1];        // token0
    float4 xa1 = xq[32 + qb], xb1 = xq[32 + qb + 1];   // token1

    // ---- W_in as float2: W_in[d][2ep..2ep+1], d = dbase..dbase+7 ----
    const float2* Wi2 = reinterpret_cast<const float2*>(W_in);
    float2 wi[8];
    #pragma unroll
    for (int i = 0; i < 8; i++) wi[i] = Wi2[(dbase + i) * (DC / 2) + ep];

    // ---- mask-independent W_out / bias prefetch (shared by both tokens) ----
    float wo[DC];
    #pragma unroll
    for (int e = 0; e < DC; e++) wo[e] = W_out[e * DIM + t];
    float bo = b_out[t];

    // ---- z partials: 8 dims x 2 e's x 2 tokens = 32 FMAs ----
    float2 p0 = make_float2(0.f, 0.f), p1 = make_float2(0.f, 0.f);
    #define STEP(XV0, XV1, I) \
        p0.x = fmaf((XV0), wi[I].x, p0.x); p0.y = fmaf((XV0), wi[I].y, p0.y); \
        p1.x = fmaf((XV1), wi[I].x, p1.x); p1.y = fmaf((XV1), wi[I].y, p1.y);
    STEP(xa0.x, xa1.x, 0) STEP(xa0.y, xa1.y, 1)
    STEP(xa0.z, xa1.z, 2) STEP(xa0.w, xa1.w, 3)
    STEP(xb0.x, xb1.x, 4) STEP(xb0.y, xb1.y, 5)
    STEP(xb0.z, xb1.z, 6) STEP(xb0.w, xb1.w, 7)
    #undef STEP

    // ---- wsum precompute (mask-independent, off the critical path):
    //      out = bo + sum_e s_e*wo_e = 2*sum_{set} wo_e + (bo - sum_all wo_e) ----
    float ws01 = (wo[0] + wo[1])   + (wo[2] + wo[3]);
    float ws23 = (wo[4] + wo[5])   + (wo[6] + wo[7]);
    float ws45 = (wo[8] + wo[9])   + (wo[10] + wo[11]);
    float ws67 = (wo[12] + wo[13]) + (wo[14] + wo[15]);
    float base = bo - ((ws01 + ws23) + (ws45 + ws67));

    // ---- warp pre-reduce over the 4 chunks (xor 8, then 16): 8 shfls ----
    p0.x += __shfl_xor_sync(FULL, p0.x, 8);
    p0.y += __shfl_xor_sync(FULL, p0.y, 8);
    p1.x += __shfl_xor_sync(FULL, p1.x, 8);
    p1.y += __shfl_xor_sync(FULL, p1.y, 8);
    p0.x += __shfl_xor_sync(FULL, p0.x, 16);
    p0.y += __shfl_xor_sync(FULL, p0.y, 16);
    p1.x += __shfl_xor_sync(FULL, p1.x, 16);
    p1.y += __shfl_xor_sync(FULL, p1.y, 16);

    if (lane < 8) {
        sm[warp][0][ep] = p0;
        sm[warp][1][ep] = p1;
    }
    __syncthreads();

    // ---- split-half final reduce: lane l handles token l>>4, dim l&15.
    //      offset collapses to smf[w*32 + lane] -> uniform, conflict-free ----
    const float* smf = reinterpret_cast<const float*>(sm);
    float z = ((smf[lane] + smf[32 + lane]) + (smf[64 + lane] + smf[96 + lane]))
            + b_in[lane & 15];

    // one ballot gives both masks; bit e = (z_e > 0); tie z==0 -> 0 (argmin lowest idx)
    unsigned b = __ballot_sync(FULL, z > 0.0f);
    unsigned mask0 = b & 0xFFFFu;
    unsigned mask1 = b >> 16;

    // ---- masked sums via predicated adds; two chains per token ----
    float a0 = 0.f, c0 = 0.f, a1 = 0.f, c1 = 0.f;
    #define ACC(E, A0, A1) { \
        if (mask0 & (1u << (E))) A0 += wo[E]; \
        if (mask1 & (1u << (E))) A1 += wo[E]; }
    ACC(0,  a0, a1); ACC(1,  c0, c1);
    ACC(2,  a0, a1); ACC(3,  c0, c1);
    ACC(4,  a0, a1); ACC(5,  c0, c1);
    ACC(6,  a0, a1); ACC(7,  c0, c1);
    ACC(8,  a0, a1); ACC(9,  c0, c1);
    ACC(10, a0, a1); ACC(11, c0, c1);
    ACC(12, a0, a1); ACC(13, c0, c1);
    ACC(14, a0, a1); ACC(15, c0, c1);
    #undef ACC

    float* op = out + (size_t)token0 * DIM;
    op[t]       = fmaf(2.0f, a0 + c0, base);
    op[DIM + t] = fmaf(2.0f, a1 + c1, base);

    if (write_indices && t == 0) {
        float2 idx = make_float2((float)(__brev(mask0) >> 16),
                                 (float)(__brev(mask1) >> 16));
        *reinterpret_cast<float2*>(out + (size_t)N_TOKENS * DIM + token0) = idx;
    }
}

extern "C" void kernel_launch(void* const* d_in, const int* in_sizes, int n_in,
                              void* d_out, int out_size)
{
    const float* x     = (const float*)d_in[0];
    const float* W_in  = (const float*)d_in[1];
    const float* b_in  = (const float*)d_in[2];
    const float* W_out = (const float*)d_in[3];
    const float* b_out = (const float*)d_in[4];
    float* out = (float*)d_out;

    int write_indices = (out_size >= N_TOKENS * DIM + N_TOKENS) ? 1 : 0;

    flf_quant_k11<<<GRID_BLOCKS, DIM>>>(x, W_in, b_in, W_out, b_out, out, write_indices);
}